// round 15
// baseline (speedup 1.0000x reference)
#include <cuda_runtime.h>
#include <math.h>

#define NMAX 110592
#define EMAX (NMAX*8)
#define PTOT 512

static __device__ __align__(16) float g_H1 [NMAX*64];
static __device__ __align__(16) float g_EMB[NMAX*64];
static __device__ int   g_deg[NMAX];        // invariant: zero at kernel_launch entry
static __device__ int   g_ptr[NMAX+1];
static __device__ int   g_cur[NMAX];
static __device__ int   g_adj[EMAX];
static __device__ int   g_bsum[160];
static __device__ int   g_boff[160];
static __device__ int   g_cnt;
static __device__ int   g_done;
static __device__ int   g_pass;
static __device__ int   g_done2;
static __device__ int   g_flag0;
static __device__ int   g_flag;
static __device__ int   g_flag2;
static __device__ int   g_offs[PTOT];
static __device__ int   g_offt[PTOT];
static __device__ int   g_order[PTOT];
static __device__ __align__(16) float g_virt[64];

// ---------------- packed fp32x2 helpers ----------------
__device__ __forceinline__ void fma2(unsigned long long& d, unsigned long long a, unsigned long long b) {
    asm("fma.rn.f32x2 %0, %1, %2, %0;" : "+l"(d) : "l"(a), "l"(b));
}
__device__ __forceinline__ unsigned long long splat2(float x) {
    unsigned long long r; asm("mov.b64 %0, {%1, %1};" : "=l"(r) : "f"(x)); return r;
}
__device__ __forceinline__ unsigned long long pack2(float x, float y) {
    unsigned long long r; asm("mov.b64 %0, {%1, %2};" : "=l"(r) : "f"(x), "f"(y)); return r;
}
__device__ __forceinline__ float2 unpack2(unsigned long long v) {
    float2 f; asm("mov.b64 {%0, %1}, %2;" : "=f"(f.x), "=f"(f.y) : "l"(v)); return f;
}

// dummy kernel: shifts gnn12 into the ncu capture slot (4th launch)
__global__ void k_nop() {}

// ---------------- one resident kernel: count / offsets / scan / fill ----------------
__global__ __launch_bounds__(1024) void k_all(
        const int* __restrict__ ls, const int* __restrict__ lt,
        const float* __restrict__ virt,
        const int* __restrict__ eis, int Es,
        const int* __restrict__ eit, int Et, int Ns,
        int Ntot, int NB, int Etot) {
    __shared__ int ws[32];
    __shared__ int s_t0, s_t1, s_t2;
    __shared__ int bs[160];
    int t = threadIdx.x, lane = t & 31, w = t >> 5, bid = blockIdx.x;
    int stride = NB * 1024;

    for (int e = bid * 1024 + t; e < Etot; e += stride) {
        if (e < Es) atomicAdd(&g_deg[eis[Es + e]], 1);
        else { int k = e - Es; atomicAdd(&g_deg[eit[Et + k] + Ns], 1); }
    }
    if (bid == 0) {
        if (t < PTOT) {
            int accs = 0, acct = 0;
            for (int p = 0; p < PTOT; p++) {
                int c = (p < t);
                accs += c ? ls[p] : 0;
                acct += c ? lt[p] : 0;
            }
            g_offs[t] = accs;
            g_offt[t] = acct;
            int n_t = ls[t], rank = 0;
            for (int p = 0; p < PTOT; p++) {
                int np = ls[p];
                rank += (np > n_t) || (np == n_t && p < t);
            }
            g_order[rank] = t;
        }
        if (t < 64) {
            float s = 0.f;
            for (int j = 0; j < 64; j++) { float v = virt[j]; s += v * v; }
            g_virt[t] = virt[t] * rsqrtf(fmaxf(s, 1e-24f));
        }
    }
    __threadfence();
    if (t == 0) s_t0 = atomicAdd(&g_cnt, 1);
    __syncthreads();
    if (s_t0 == NB - 1) {
        if (t == 0) { g_cnt = 0; __threadfence(); atomicExch(&g_flag0, 1); }
    }
    if (t == 0) { while (atomicAdd(&g_flag0, 0) == 0) {} }
    __syncthreads();

    int i = bid * 1024 + t;
    int a = (i < Ntot) ? g_deg[i] : 0;
    if (i < Ntot) g_deg[i] = 0;
    int v = a;
    #pragma unroll
    for (int d = 1; d < 32; d <<= 1) { int u = __shfl_up_sync(0xffffffffu, v, d); if (lane >= d) v += u; }
    if (lane == 31) ws[w] = v;
    __syncthreads();
    if (w == 0) {
        int x = ws[lane];
        #pragma unroll
        for (int d = 1; d < 32; d <<= 1) { int u = __shfl_up_sync(0xffffffffu, x, d); if (lane >= d) x += u; }
        ws[lane] = x;
    }
    __syncthreads();
    int excl = v - a + (w > 0 ? ws[w - 1] : 0);
    if (i < Ntot) g_ptr[i] = excl;
    if (t == 0) g_bsum[bid] = ws[31];
    __threadfence();
    if (t == 0) s_t1 = atomicAdd(&g_done, 1);
    __syncthreads();
    if (s_t1 == NB - 1) {
        int bv = (t < NB) ? g_bsum[t] : 0;
        if (t < 160) bs[t] = (t < NB) ? bv : 0;
        __syncthreads();
        for (int d = 1; d < 160; d <<= 1) {
            int x = (t >= d && t < NB) ? bs[t - d] : 0;
            __syncthreads();
            if (t < NB) bs[t] += x;
            __syncthreads();
        }
        if (t < NB) g_boff[t] = bs[t] - bv;
        if (t == NB - 1) g_ptr[Ntot] = bs[t];
        if (t == 0) { g_done = 0; __threadfence(); atomicExch(&g_flag, 1); }
    }
    if (t == 0) { while (atomicAdd(&g_flag, 0) == 0) {} }
    __syncthreads();
    if (i < Ntot) {
        int p = g_ptr[i] + g_boff[bid];
        g_ptr[i] = p;
        g_cur[i] = p;
    }
    __threadfence();
    __syncthreads();
    if (t == 0) s_t2 = atomicAdd(&g_pass, 1);
    __syncthreads();
    if (s_t2 == NB - 1) {
        if (t == 0) { g_pass = 0; __threadfence(); atomicExch(&g_flag2, 1); }
    }
    if (t == 0) { while (atomicAdd(&g_flag2, 0) == 0) {} }
    __syncthreads();

    for (int e = bid * 1024 + t; e < Etot; e += stride) {
        if (e < Es) {
            int pos = atomicAdd(&g_cur[eis[Es + e]], 1);
            g_adj[pos] = eis[e];
        } else {
            int k = e - Es;
            int pos = atomicAdd(&g_cur[eit[Et + k] + Ns], 1);
            g_adj[pos] = eit[k] + Ns;
        }
    }
    __threadfence();
    __syncthreads();
    if (t == 0) {
        int c = atomicAdd(&g_done2, 1);
        if (c == NB - 1) {
            g_done2 = 0;
            atomicExch(&g_flag0, 0);
            atomicExch(&g_flag, 0);
            atomicExch(&g_flag2, 0);
        }
    }
}

// warp bitonic sort of 32 ints (ascending)
__device__ __forceinline__ int bsort32(int v, int lane) {
    #pragma unroll
    for (int k = 2; k <= 32; k <<= 1) {
        #pragma unroll
        for (int j = k >> 1; j > 0; j >>= 1) {
            int o = __shfl_xor_sync(0xffffffffu, v, j);
            bool up  = ((lane & k) == 0);
            bool low = ((lane & j) == 0);
            v = (up == low) ? min(v, o) : max(v, o);
        }
    }
    return v;
}

__device__ __forceinline__ const float* xrow(int node, const float* xs, const float* xt, int Ns) {
    return (node < Ns) ? (xs + (size_t)node * 32) : (xt + (size_t)(node - Ns) * 32);
}

// packed GEMM accumulate: acc += As[K][68] x Ws[K][64]; 256 threads, 4x4 tiles
template <int K>
__device__ __forceinline__ void gemm_acc2(const float* As, const float* Ws,
                                          unsigned long long acc[4][2], int tid) {
    int ti = tid >> 4, tj = tid & 15;
    unsigned bbase = (unsigned)__cvta_generic_to_shared(Ws + 4 * tj);
    const float* ap = As + 4 * ti;
    #pragma unroll 4
    for (int k = 0; k < K; k++) {
        float4 a = *(const float4*)(ap + k * 68);
        unsigned long long b01, b23;
        asm("ld.shared.v2.u64 {%0, %1}, [%2];" : "=l"(b01), "=l"(b23)
            : "r"(bbase + (unsigned)(k * 256)));
        unsigned long long a0 = splat2(a.x), a1 = splat2(a.y), a2 = splat2(a.z), a3 = splat2(a.w);
        fma2(acc[0][0], a0, b01); fma2(acc[0][1], a0, b23);
        fma2(acc[1][0], a1, b01); fma2(acc[1][1], a1, b23);
        fma2(acc[2][0], a2, b01); fma2(acc[2][1], a2, b23);
        fma2(acc[3][0], a3, b01); fma2(acc[3][1], a3, b23);
    }
}

// ---------- GNN layer 0 (256 threads, 4x4 tiles) ----------
__global__ __launch_bounds__(256) void k_gnn0(const float* __restrict__ W0,
        const float* __restrict__ W1, const float* __restrict__ bias, int Ntot,
        const float* __restrict__ xs, const float* __restrict__ xt, int Ns) {
    __shared__ float As[64 * 68];
    __shared__ float Ws[64 * 64];
    int node0 = blockIdx.x * 64, tid = threadIdx.x, w = tid >> 5, lane = tid & 31;

    for (int idx = tid; idx < 64 * 64; idx += 256) {
        int k = idx >> 6, f = idx & 63;
        Ws[idx] = (k < 32) ? W0[k * 64 + f] : W1[(k - 32) * 64 + f];
    }
    #pragma unroll
    for (int s = 0; s < 8; s++) {
        int nd = w * 8 + s, node = node0 + nd;
        float agg = 0.f, selfv = 0.f;
        if (node < Ntot) {
            int p0 = __shfl_sync(0xffffffffu, (lane == 0) ? g_ptr[node] : 0, 0);
            int p1 = __shfl_sync(0xffffffffu, (lane == 0) ? g_ptr[node + 1] : 0, 0);
            int deg = p1 - p0;
            if (deg <= 32) {
                int v = (lane < deg) ? g_adj[p0 + lane] : 0x7fffffff;
                v = bsort32(v, lane);
                if (lane < deg) g_adj[p0 + lane] = v;
                for (int e = 0; e < deg; e++) {
                    int a = __shfl_sync(0xffffffffu, v, e);
                    agg += xrow(a, xs, xt, Ns)[lane];
                }
            } else {
                if (lane == 0) {
                    for (int a = p0 + 1; a < p1; a++) {
                        int key = g_adj[a]; int b = a - 1;
                        while (b >= p0 && g_adj[b] > key) { g_adj[b + 1] = g_adj[b]; b--; }
                        g_adj[b + 1] = key;
                    }
                }
                __syncwarp();
                for (int e = p0; e < p1; e++) agg += xrow(g_adj[e], xs, xt, Ns)[lane];
            }
            selfv = xrow(node, xs, xt, Ns)[lane];
        }
        As[lane * 68 + nd] = agg;
        As[(lane + 32) * 68 + nd] = selfv;
    }
    __syncthreads();
    {
        int ti = tid >> 4, tj = tid & 15;
        unsigned long long acc[4][2] = {{0,0},{0,0},{0,0},{0,0}};
        gemm_acc2<64>(As, Ws, acc, tid);
        float4 bb = *(const float4*)&bias[4 * tj];
        #pragma unroll
        for (int r = 0; r < 4; r++) {
            int node = node0 + 4 * ti + r;
            float2 lo = unpack2(acc[r][0]), hi = unpack2(acc[r][1]);
            float4 o;
            o.x = fmaxf(lo.x + bb.x, 0.f); o.y = fmaxf(lo.y + bb.y, 0.f);
            o.z = fmaxf(hi.x + bb.z, 0.f); o.w = fmaxf(hi.y + bb.w, 0.f);
            if (node < Ntot) *(float4*)&g_H1[(size_t)node * 64 + 4 * tj] = o;
        }
    }
}

// ---------- fused GNN layer 1 + projection, chunked-K (256 threads) ----------
__global__ __launch_bounds__(256) void k_gnn12(
        const float* __restrict__ Wr1, const float* __restrict__ Wo1,
        const float* __restrict__ b1,
        const float* __restrict__ We, const float* __restrict__ be, int Ntot,
        const float* __restrict__ xs, const float* __restrict__ xt, int Ns) {
    extern __shared__ float sm[];
    float* A1  = sm;              // [64][68]
    float* A2  = sm + 4352;       // [64][68] (H1 self)
    float* H2s = sm + 8704;       // [64][68] node-major
    float* Ws  = sm + 13056;      // [64][64]
    int node0 = blockIdx.x * 64, tid = threadIdx.x, w = tid >> 5, lane = tid & 31;
    int ti = tid >> 4, tj = tid & 15;

    #pragma unroll
    for (int s = 0; s < 8; s++) {
        int nd = w * 8 + s, node = node0 + nd;
        float a0 = 0.f, a1 = 0.f, s0 = 0.f, s1 = 0.f;
        if (node < Ntot) {
            int p0 = __shfl_sync(0xffffffffu, (lane == 0) ? g_ptr[node] : 0, 0);
            int p1 = __shfl_sync(0xffffffffu, (lane == 0) ? g_ptr[node + 1] : 0, 0);
            for (int e = p0; e < p1; e++) {
                size_t r = (size_t)g_adj[e] * 64;
                a0 += g_H1[r + lane];
                a1 += g_H1[r + 32 + lane];
            }
            size_t rn = (size_t)node * 64;
            s0 = g_H1[rn + lane];
            s1 = g_H1[rn + 32 + lane];
        }
        A1[lane * 68 + nd]        = a0;
        A1[(lane + 32) * 68 + nd] = a1;
        A2[lane * 68 + nd]        = s0;
        A2[(lane + 32) * 68 + nd] = s1;
    }
    for (int idx = tid; idx < 4096; idx += 256) Ws[idx] = Wr1[idx];
    __syncthreads();

    unsigned long long acc[4][2] = {{0,0},{0,0},{0,0},{0,0}};
    gemm_acc2<64>(A1, Ws, acc, tid);
    __syncthreads();
    for (int idx = tid; idx < 4096; idx += 256) Ws[idx] = Wo1[idx];
    __syncthreads();
    gemm_acc2<64>(A2, Ws, acc, tid);
    {
        float4 bb = *(const float4*)&b1[4 * tj];
        #pragma unroll
        for (int r = 0; r < 4; r++) {
            float2 lo = unpack2(acc[r][0]), hi = unpack2(acc[r][1]);
            float4 o;
            o.x = fmaxf(lo.x + bb.x, 0.f); o.y = fmaxf(lo.y + bb.y, 0.f);
            o.z = fmaxf(hi.x + bb.z, 0.f); o.w = fmaxf(hi.y + bb.w, 0.f);
            *(float4*)&H2s[(4 * ti + r) * 68 + 4 * tj] = o;
        }
    }
    __syncthreads();

    unsigned long long acc2[4][2] = {{0,0},{0,0},{0,0},{0,0}};
    for (int idx = tid; idx < 2048; idx += 256) Ws[idx] = We[idx];
    for (int idx = tid; idx < 2048; idx += 256) {
        int nd = idx >> 5, k = idx & 31;
        int node = node0 + nd;
        A1[k * 68 + nd] = (node < Ntot) ? xrow(node, xs, xt, Ns)[k] : 0.f;
    }
    __syncthreads();
    gemm_acc2<32>(A1, Ws, acc2, tid);
    __syncthreads();
    for (int idx = tid; idx < 4096; idx += 256) Ws[idx] = We[32 * 64 + idx];
    for (int idx = tid; idx < 4096; idx += 256) {
        int nd = idx >> 6, k = idx & 63;
        A1[k * 68 + nd] = H2s[nd * 68 + k];
    }
    __syncthreads();
    gemm_acc2<64>(A2, Ws, acc2, tid);
    __syncthreads();
    for (int idx = tid; idx < 4096; idx += 256) Ws[idx] = We[96 * 64 + idx];
    __syncthreads();
    gemm_acc2<64>(A1, Ws, acc2, tid);
    {
        float4 bb = *(const float4*)&be[4 * tj];
        #pragma unroll
        for (int r = 0; r < 4; r++) {
            int node = node0 + 4 * ti + r;
            float2 lo = unpack2(acc2[r][0]), hi = unpack2(acc2[r][1]);
            float4 o;
            o.x = lo.x + bb.x; o.y = lo.y + bb.y;
            o.z = hi.x + bb.z; o.w = hi.y + bb.w;
            float ss = o.x*o.x + o.y*o.y + o.z*o.z + o.w*o.w;
            #pragma unroll
            for (int d = 1; d < 16; d <<= 1) ss += __shfl_xor_sync(0xffffffffu, ss, d);
            float inv = rsqrtf(fmaxf(ss, 1e-24f));
            o.x *= inv; o.y *= inv; o.z *= inv; o.w *= inv;
            if (node < Ntot) *(float4*)&g_EMB[(size_t)node * 64 + 4 * tj] = o;
        }
    }
}

// ---------------- per-pair: cost/K + Sinkhorn + gamma/cost/geds (512 threads) ----------------
// rows of g_EMB and g_virt are unit-norm -> d = 2 - 2*dot
__global__ __launch_bounds__(512) void k_pair(const int* __restrict__ ls, const int* __restrict__ lt,
        int Ns, float* __restrict__ gamma, float* __restrict__ cost, float* __restrict__ geds2) {
    extern __shared__ float sm[];
    float* Km   = sm;               // [192][192]
    float* Ssub = sm + 36864;       // [64][68]
    float* Tsub = Ssub + 4352;      // 2 x [64][68]
    float* uu   = Tsub + 8704;      // [192]
    float* vv   = uu + 192;         // [192]
    float* vp   = vv + 192;         // [192]
    float* red  = vp + 192;         // [512]

    int p = g_order[blockIdx.x];
    int tid = threadIdx.x;
    int n = ls[p], m = lt[p], q = 192 - n;
    int offs = g_offs[p], offt = g_offt[p];
    const float* EB = g_EMB;

    for (int i = tid; i < 192; i += 512) {
        uu[i] = 1.0f / 192.0f;
        vv[i] = (i >= n && q > 0) ? (192.0f / (float)q) : 0.f;
    }

    // cost/K for real tiles (two 64x64 tiles concurrently, one per 256-thread group)
    int g = tid >> 8, lt5 = tid & 255;
    int ti = lt5 >> 4, tj = lt5 & 15;
    float* Tg = Tsub + g * 4352;
    int ntile = (n + 63) >> 6;

    for (int it_i = 0; it_i < ntile; it_i++) {
        int i0 = it_i << 6;
        __syncthreads();
        for (int idx = tid; idx < 4096; idx += 512) {
            int nd = idx >> 6, k = idx & 63;
            int i = i0 + nd; if (i >= n) i = n - 1;
            Ssub[k * 68 + nd] = EB[(size_t)(offs + i) * 64 + k];
        }
        for (int jj = 0; jj < ntile; jj += 2) {
            int jt = jj + g;
            bool mine = (jt < ntile);
            int j0 = jt << 6;
            __syncthreads();
            if (mine) {
                for (int idx = lt5; idx < 4096; idx += 256) {
                    int nd = idx >> 6, k = idx & 63;
                    int j = j0 + nd;
                    const float* r = (j < m) ? (EB + (size_t)(Ns + offt + j) * 64) : g_virt;
                    Tg[k * 68 + nd] = r[k];
                }
            }
            __syncthreads();
            if (mine) {
                unsigned long long acc[4][2] = {{0,0},{0,0},{0,0},{0,0}};
                unsigned bbase = (unsigned)__cvta_generic_to_shared(Tg + 4 * tj);
                const float* ap = Ssub + 4 * ti;
                #pragma unroll 4
                for (int k = 0; k < 64; k++) {
                    float4 a = *(const float4*)(ap + k * 68);
                    unsigned long long b01, b23;
                    asm("ld.shared.v2.u64 {%0, %1}, [%2];" : "=l"(b01), "=l"(b23)
                        : "r"(bbase + (unsigned)(k * 272)));
                    unsigned long long a0 = splat2(a.x), a1 = splat2(a.y),
                                       a2 = splat2(a.z), a3 = splat2(a.w);
                    fma2(acc[0][0], a0, b01); fma2(acc[0][1], a0, b23);
                    fma2(acc[1][0], a1, b01); fma2(acc[1][1], a1, b23);
                    fma2(acc[2][0], a2, b01); fma2(acc[2][1], a2, b23);
                    fma2(acc[3][0], a3, b01); fma2(acc[3][1], a3, b23);
                }
                #pragma unroll
                for (int r = 0; r < 4; r++) {
                    int i = i0 + 4 * ti + r;
                    float2 lo = unpack2(acc[r][0]), hi = unpack2(acc[r][1]);
                    float af[4] = {lo.x, lo.y, hi.x, hi.y};
                    float kv[4];
                    #pragma unroll
                    for (int c = 0; c < 4; c++) {
                        int j = j0 + 4 * tj + c;
                        if (i < n && j < n) {
                            float d = fmaxf(2.0f - 2.0f * af[c], 1e-12f);
                            float cd = d * rsqrtf(d);
                            kv[c] = __expf(-10.0f * cd);
                        } else {
                            kv[c] = ((i >= n) && (j >= n)) ? 1.f : 0.f;
                        }
                    }
                    *(float4*)&Km[i * 192 + j0 + 4 * tj] = make_float4(kv[0], kv[1], kv[2], kv[3]);
                }
            }
        }
    }
    __syncthreads();

    // Sinkhorn on the n x n real block; pad u,v stationary; cross K = 0 exactly.
    int nh = (n >> 1) & ~1;   // even split point
    for (int it = 0; it < 8; it++) {
        // v-pass: columns, two row-halves in parallel
        float slo = 0.f;
        if (tid < 192) {
            int j = tid;
            if (j < n) {
                unsigned long long s2 = 0;
                for (int i = 0; i < nh; i += 2) {
                    unsigned long long kk = pack2(Km[i * 192 + j], Km[(i + 1) * 192 + j]);
                    unsigned long long u2 = *(const unsigned long long*)(uu + i);
                    fma2(s2, kk, u2);
                }
                float2 f = unpack2(s2);
                slo = f.x + f.y;
            }
        } else if (tid < 384) {
            int j = tid - 192;
            if (j < n) {
                unsigned long long s2 = 0;
                float st = 0.f;
                int i = nh;
                for (; i + 2 <= n; i += 2) {
                    unsigned long long kk = pack2(Km[i * 192 + j], Km[(i + 1) * 192 + j]);
                    unsigned long long u2 = *(const unsigned long long*)(uu + i);
                    fma2(s2, kk, u2);
                }
                if (i < n) st = Km[i * 192 + j] * uu[i];
                float2 f = unpack2(s2);
                vp[j] = f.x + f.y + st;
            }
        }
        __syncthreads();
        if (tid < 192 && tid < n) vv[tid] = 1.0f / (slo + vp[tid]);
        __syncthreads();
        // u-pass: diagonal-staggered thread-per-row, two column-halves in parallel,
        // dual accumulators to halve the dependent-FMA chain
        float sA = 0.f;
        if (tid < 192) {
            int r = tid;
            if (r < n) {
                const float* row = Km + r * 192;
                int st = r & 31; if (st >= nh) st = 0;
                float s0 = 0.f, s1 = 0.f;
                int k = st;
                for (; k + 1 < nh; k += 2) {
                    s0 = fmaf(row[k], vv[k], s0);
                    s1 = fmaf(row[k + 1], vv[k + 1], s1);
                }
                if (k < nh) s0 = fmaf(row[k], vv[k], s0);
                k = 0;
                for (; k + 1 < st; k += 2) {
                    s0 = fmaf(row[k], vv[k], s0);
                    s1 = fmaf(row[k + 1], vv[k + 1], s1);
                }
                if (k < st) s0 = fmaf(row[k], vv[k], s0);
                sA = s0 + s1;
            }
        } else if (tid < 384) {
            int r = tid - 192;
            if (r < n) {
                const float* row = Km + r * 192;
                int wd = n - nh;
                int so = r & 31; if (so >= wd) so = 0;
                int st = nh + so;
                float s0 = 0.f, s1 = 0.f;
                int k = st;
                for (; k + 1 < n; k += 2) {
                    s0 = fmaf(row[k], vv[k], s0);
                    s1 = fmaf(row[k + 1], vv[k + 1], s1);
                }
                if (k < n) s0 = fmaf(row[k], vv[k], s0);
                k = nh;
                for (; k + 1 < st; k += 2) {
                    s0 = fmaf(row[k], vv[k], s0);
                    s1 = fmaf(row[k + 1], vv[k + 1], s1);
                }
                if (k < st) s0 = fmaf(row[k], vv[k], s0);
                vp[r] = s0 + s1;
            }
        }
        __syncthreads();
        if (tid < 192 && tid < n) uu[tid] = 1.0f / (sA + vp[tid]);
        __syncthreads();
    }

    // epilogue: gamma = u K v; cost = -0.1 ln K in-block, pattern elsewhere; geds
    float* costp = cost + (size_t)p * 36864;
    float* gamp  = gamma + (size_t)p * 36864;
    float loc = 0.f;
    for (int idx = tid; idx < 9216; idx += 512) {
        int i = idx / 48, jb = (idx - i * 48) * 4;
        float4 k4 = *(const float4*)&Km[i * 192 + jb];   // garbage outside real tiles: discarded
        float ui = uu[i];
        float kk[4] = {k4.x, k4.y, k4.z, k4.w};
        float gg[4], cc[4];
        #pragma unroll
        for (int c = 0; c < 4; c++) {
            int j = jb + c;
            bool inb = (i < n) && (j < n);
            bool pad = (i >= n) && (j >= n);
            float kv = inb ? kk[c] : (pad ? 1.f : 0.f);
            cc[c] = inb ? (-0.1f * __logf(kk[c])) : (pad ? 0.f : 1000.f);
            gg[c] = ui * kv * vv[j];
            loc += gg[c] * cc[c];
        }
        *(float4*)&gamp[i * 192 + jb]  = make_float4(gg[0], gg[1], gg[2], gg[3]);
        *(float4*)&costp[i * 192 + jb] = make_float4(cc[0], cc[1], cc[2], cc[3]);
    }
    red[tid] = loc;
    __syncthreads();
    #pragma unroll
    for (int s = 256; s; s >>= 1) { if (tid < s) red[tid] += red[tid + s]; __syncthreads(); }
    if (tid == 0) geds2[p] = red[0] / (float)(n + m);
}

extern "C" void kernel_launch(void* const* d_in, const int* in_sizes, int n_in,
                              void* d_out, int out_size) {
    const float* x_s     = (const float*)d_in[0];
    const float* x_t     = (const float*)d_in[1];
    const float* W_rel0  = (const float*)d_in[2];
    const float* b_rel0  = (const float*)d_in[3];
    const float* W_root0 = (const float*)d_in[4];
    const float* W_rel1  = (const float*)d_in[5];
    const float* b_rel1  = (const float*)d_in[6];
    const float* W_root1 = (const float*)d_in[7];
    const float* W_e     = (const float*)d_in[8];
    const float* b_e     = (const float*)d_in[9];
    const float* virt    = (const float*)d_in[10];
    const int* ei_s      = (const int*)d_in[11];
    const int* ei_t      = (const int*)d_in[12];
    const int* len_s     = (const int*)d_in[13];
    const int* len_t     = (const int*)d_in[14];

    int Ns = in_sizes[0] / 32, Nt = in_sizes[1] / 32;
    int Es = in_sizes[11] / 2, Et = in_sizes[12] / 2;
    int Ntot = Ns + Nt;
    int Etot = Es + Et;

    float* out   = (float*)d_out;
    float* gamma = out;
    float* cost  = out + (size_t)PTOT * 36864;
    float* geds2 = cost + (size_t)PTOT * 36864;

    cudaFuncSetAttribute(k_gnn12, cudaFuncAttributeMaxDynamicSharedMemorySize, 17152 * 4);
    cudaFuncSetAttribute(k_pair,  cudaFuncAttributeMaxDynamicSharedMemorySize, 51008 * 4);

    int NB = (Ntot + 1023) / 1024;
    k_all<<<NB, 1024>>>(len_s, len_t, virt, ei_s, Es, ei_t, Et, Ns, Ntot, NB, Etot);

    int gb = (Ntot + 63) / 64;
    k_gnn0<<<gb, 256>>>(W_rel0, W_root0, b_rel0, Ntot, x_s, x_t, Ns);
    k_nop<<<1, 32>>>();   // shifts k_gnn12 into the ncu capture slot (4th launch)
    k_gnn12<<<gb, 256, 17152 * 4>>>(W_rel1, W_root1, b_rel1, W_e, b_e, Ntot, x_s, x_t, Ns);

    k_pair<<<PTOT, 512, 51008 * 4>>>(len_s, len_t, Ns, gamma, cost, geds2);
}

// round 16
// speedup vs baseline: 1.0592x; 1.0592x over previous
#include <cuda_runtime.h>
#include <math.h>

#define NMAX 110592
#define EMAX (NMAX*8)
#define PTOT 512

static __device__ __align__(16) float g_H1 [NMAX*64];
static __device__ __align__(16) float g_EMB[NMAX*64];
static __device__ int   g_deg[NMAX];        // invariant: zero at kernel_launch entry
static __device__ int   g_ptr[NMAX+1];
static __device__ int   g_cur[NMAX];
static __device__ int   g_adj[EMAX];
static __device__ int   g_bsum[160];
static __device__ int   g_boff[160];
static __device__ int   g_cnt;
static __device__ int   g_done;
static __device__ int   g_pass;
static __device__ int   g_done2;
static __device__ int   g_flag0;
static __device__ int   g_flag;
static __device__ int   g_flag2;
static __device__ int   g_offs[PTOT];
static __device__ int   g_offt[PTOT];
static __device__ int   g_order[PTOT];
static __device__ __align__(16) float g_virt[64];

// ---------------- packed fp32x2 helpers ----------------
__device__ __forceinline__ void fma2(unsigned long long& d, unsigned long long a, unsigned long long b) {
    asm("fma.rn.f32x2 %0, %1, %2, %0;" : "+l"(d) : "l"(a), "l"(b));
}
__device__ __forceinline__ unsigned long long splat2(float x) {
    unsigned long long r; asm("mov.b64 %0, {%1, %1};" : "=l"(r) : "f"(x)); return r;
}
__device__ __forceinline__ unsigned long long pack2(float x, float y) {
    unsigned long long r; asm("mov.b64 %0, {%1, %2};" : "=l"(r) : "f"(x), "f"(y)); return r;
}
__device__ __forceinline__ float2 unpack2(unsigned long long v) {
    float2 f; asm("mov.b64 {%0, %1}, %2;" : "=f"(f.x), "=f"(f.y) : "l"(v)); return f;
}

// ---------------- one resident kernel: count / offsets / scan / fill ----------------
__global__ __launch_bounds__(1024) void k_all(
        const int* __restrict__ ls, const int* __restrict__ lt,
        const float* __restrict__ virt,
        const int* __restrict__ eis, int Es,
        const int* __restrict__ eit, int Et, int Ns,
        int Ntot, int NB, int Etot) {
    __shared__ int ws[32];
    __shared__ int s_t0, s_t1, s_t2;
    __shared__ int bs[160];
    int t = threadIdx.x, lane = t & 31, w = t >> 5, bid = blockIdx.x;
    int stride = NB * 1024;

    for (int e = bid * 1024 + t; e < Etot; e += stride) {
        if (e < Es) atomicAdd(&g_deg[eis[Es + e]], 1);
        else { int k = e - Es; atomicAdd(&g_deg[eit[Et + k] + Ns], 1); }
    }
    if (bid == 0) {
        if (t < PTOT) {
            int accs = 0, acct = 0;
            for (int p = 0; p < PTOT; p++) {
                int c = (p < t);
                accs += c ? ls[p] : 0;
                acct += c ? lt[p] : 0;
            }
            g_offs[t] = accs;
            g_offt[t] = acct;
            int n_t = ls[t], rank = 0;
            for (int p = 0; p < PTOT; p++) {
                int np = ls[p];
                rank += (np > n_t) || (np == n_t && p < t);
            }
            g_order[rank] = t;
        }
        if (t < 64) {
            float s = 0.f;
            for (int j = 0; j < 64; j++) { float v = virt[j]; s += v * v; }
            g_virt[t] = virt[t] * rsqrtf(fmaxf(s, 1e-24f));
        }
    }
    __threadfence();
    if (t == 0) s_t0 = atomicAdd(&g_cnt, 1);
    __syncthreads();
    if (s_t0 == NB - 1) {
        if (t == 0) { g_cnt = 0; __threadfence(); atomicExch(&g_flag0, 1); }
    }
    if (t == 0) { while (atomicAdd(&g_flag0, 0) == 0) {} }
    __syncthreads();

    int i = bid * 1024 + t;
    int a = (i < Ntot) ? g_deg[i] : 0;
    if (i < Ntot) g_deg[i] = 0;
    int v = a;
    #pragma unroll
    for (int d = 1; d < 32; d <<= 1) { int u = __shfl_up_sync(0xffffffffu, v, d); if (lane >= d) v += u; }
    if (lane == 31) ws[w] = v;
    __syncthreads();
    if (w == 0) {
        int x = ws[lane];
        #pragma unroll
        for (int d = 1; d < 32; d <<= 1) { int u = __shfl_up_sync(0xffffffffu, x, d); if (lane >= d) x += u; }
        ws[lane] = x;
    }
    __syncthreads();
    int excl = v - a + (w > 0 ? ws[w - 1] : 0);
    if (i < Ntot) g_ptr[i] = excl;
    if (t == 0) g_bsum[bid] = ws[31];
    __threadfence();
    if (t == 0) s_t1 = atomicAdd(&g_done, 1);
    __syncthreads();
    if (s_t1 == NB - 1) {
        int bv = (t < NB) ? g_bsum[t] : 0;
        if (t < 160) bs[t] = (t < NB) ? bv : 0;
        __syncthreads();
        for (int d = 1; d < 160; d <<= 1) {
            int x = (t >= d && t < NB) ? bs[t - d] : 0;
            __syncthreads();
            if (t < NB) bs[t] += x;
            __syncthreads();
        }
        if (t < NB) g_boff[t] = bs[t] - bv;
        if (t == NB - 1) g_ptr[Ntot] = bs[t];
        if (t == 0) { g_done = 0; __threadfence(); atomicExch(&g_flag, 1); }
    }
    if (t == 0) { while (atomicAdd(&g_flag, 0) == 0) {} }
    __syncthreads();
    if (i < Ntot) {
        int p = g_ptr[i] + g_boff[bid];
        g_ptr[i] = p;
        g_cur[i] = p;
    }
    __threadfence();
    __syncthreads();
    if (t == 0) s_t2 = atomicAdd(&g_pass, 1);
    __syncthreads();
    if (s_t2 == NB - 1) {
        if (t == 0) { g_pass = 0; __threadfence(); atomicExch(&g_flag2, 1); }
    }
    if (t == 0) { while (atomicAdd(&g_flag2, 0) == 0) {} }
    __syncthreads();

    for (int e = bid * 1024 + t; e < Etot; e += stride) {
        if (e < Es) {
            int pos = atomicAdd(&g_cur[eis[Es + e]], 1);
            g_adj[pos] = eis[e];
        } else {
            int k = e - Es;
            int pos = atomicAdd(&g_cur[eit[Et + k] + Ns], 1);
            g_adj[pos] = eit[k] + Ns;
        }
    }
    __threadfence();
    __syncthreads();
    if (t == 0) {
        int c = atomicAdd(&g_done2, 1);
        if (c == NB - 1) {
            g_done2 = 0;
            atomicExch(&g_flag0, 0);
            atomicExch(&g_flag, 0);
            atomicExch(&g_flag2, 0);
        }
    }
}

// warp bitonic sort of 32 ints (ascending)
__device__ __forceinline__ int bsort32(int v, int lane) {
    #pragma unroll
    for (int k = 2; k <= 32; k <<= 1) {
        #pragma unroll
        for (int j = k >> 1; j > 0; j >>= 1) {
            int o = __shfl_xor_sync(0xffffffffu, v, j);
            bool up  = ((lane & k) == 0);
            bool low = ((lane & j) == 0);
            v = (up == low) ? min(v, o) : max(v, o);
        }
    }
    return v;
}

__device__ __forceinline__ const float* xrow(int node, const float* xs, const float* xt, int Ns) {
    return (node < Ns) ? (xs + (size_t)node * 32) : (xt + (size_t)(node - Ns) * 32);
}

// packed GEMM accumulate: acc += As[K][68] x Ws[K][64]; 256 threads, 4x4 tiles
template <int K>
__device__ __forceinline__ void gemm_acc2(const float* As, const float* Ws,
                                          unsigned long long acc[4][2], int tid) {
    int ti = tid >> 4, tj = tid & 15;
    unsigned bbase = (unsigned)__cvta_generic_to_shared(Ws + 4 * tj);
    const float* ap = As + 4 * ti;
    #pragma unroll 4
    for (int k = 0; k < K; k++) {
        float4 a = *(const float4*)(ap + k * 68);
        unsigned long long b01, b23;
        asm("ld.shared.v2.u64 {%0, %1}, [%2];" : "=l"(b01), "=l"(b23)
            : "r"(bbase + (unsigned)(k * 256)));
        unsigned long long a0 = splat2(a.x), a1 = splat2(a.y), a2 = splat2(a.z), a3 = splat2(a.w);
        fma2(acc[0][0], a0, b01); fma2(acc[0][1], a0, b23);
        fma2(acc[1][0], a1, b01); fma2(acc[1][1], a1, b23);
        fma2(acc[2][0], a2, b01); fma2(acc[2][1], a2, b23);
        fma2(acc[3][0], a3, b01); fma2(acc[3][1], a3, b23);
    }
}

// ---------- GNN layer 0 (256 threads, 4x4 tiles) ----------
__global__ __launch_bounds__(256) void k_gnn0(const float* __restrict__ W0,
        const float* __restrict__ W1, const float* __restrict__ bias, int Ntot,
        const float* __restrict__ xs, const float* __restrict__ xt, int Ns) {
    __shared__ float As[64 * 68];
    __shared__ float Ws[64 * 64];
    int node0 = blockIdx.x * 64, tid = threadIdx.x, w = tid >> 5, lane = tid & 31;

    for (int idx = tid; idx < 64 * 64; idx += 256) {
        int k = idx >> 6, f = idx & 63;
        Ws[idx] = (k < 32) ? W0[k * 64 + f] : W1[(k - 32) * 64 + f];
    }
    #pragma unroll
    for (int s = 0; s < 8; s++) {
        int nd = w * 8 + s, node = node0 + nd;
        float agg = 0.f, selfv = 0.f;
        if (node < Ntot) {
            int p0 = __shfl_sync(0xffffffffu, (lane == 0) ? g_ptr[node] : 0, 0);
            int p1 = __shfl_sync(0xffffffffu, (lane == 0) ? g_ptr[node + 1] : 0, 0);
            int deg = p1 - p0;
            if (deg <= 32) {
                int v = (lane < deg) ? g_adj[p0 + lane] : 0x7fffffff;
                v = bsort32(v, lane);
                if (lane < deg) g_adj[p0 + lane] = v;
                for (int e = 0; e < deg; e++) {
                    int a = __shfl_sync(0xffffffffu, v, e);
                    agg += xrow(a, xs, xt, Ns)[lane];
                }
            } else {
                if (lane == 0) {
                    for (int a = p0 + 1; a < p1; a++) {
                        int key = g_adj[a]; int b = a - 1;
                        while (b >= p0 && g_adj[b] > key) { g_adj[b + 1] = g_adj[b]; b--; }
                        g_adj[b + 1] = key;
                    }
                }
                __syncwarp();
                for (int e = p0; e < p1; e++) agg += xrow(g_adj[e], xs, xt, Ns)[lane];
            }
            selfv = xrow(node, xs, xt, Ns)[lane];
        }
        As[lane * 68 + nd] = agg;
        As[(lane + 32) * 68 + nd] = selfv;
    }
    __syncthreads();
    {
        int ti = tid >> 4, tj = tid & 15;
        unsigned long long acc[4][2] = {{0,0},{0,0},{0,0},{0,0}};
        gemm_acc2<64>(As, Ws, acc, tid);
        float4 bb = *(const float4*)&bias[4 * tj];
        #pragma unroll
        for (int r = 0; r < 4; r++) {
            int node = node0 + 4 * ti + r;
            float2 lo = unpack2(acc[r][0]), hi = unpack2(acc[r][1]);
            float4 o;
            o.x = fmaxf(lo.x + bb.x, 0.f); o.y = fmaxf(lo.y + bb.y, 0.f);
            o.z = fmaxf(hi.x + bb.z, 0.f); o.w = fmaxf(hi.y + bb.w, 0.f);
            if (node < Ntot) *(float4*)&g_H1[(size_t)node * 64 + 4 * tj] = o;
        }
    }
}

// ---------- fused GNN layer 1 + projection, chunked-K, H2 transposed in-register ----------
// smem: A1 + A2 + Ws = 51.2 KB -> 4 CTAs/SM
__global__ __launch_bounds__(256) void k_gnn12(
        const float* __restrict__ Wr1, const float* __restrict__ Wo1,
        const float* __restrict__ b1,
        const float* __restrict__ We, const float* __restrict__ be, int Ntot,
        const float* __restrict__ xs, const float* __restrict__ xt, int Ns) {
    extern __shared__ float sm[];
    float* A1 = sm;              // [64][68]: agg, then H2 (k-major)
    float* A2 = sm + 4352;       // [64][68]: H1 self, then X (k-major, 32 rows)
    float* Ws = sm + 8704;       // [64][64]
    int node0 = blockIdx.x * 64, tid = threadIdx.x, w = tid >> 5, lane = tid & 31;
    int ti = tid >> 4, tj = tid & 15;

    #pragma unroll
    for (int s = 0; s < 8; s++) {
        int nd = w * 8 + s, node = node0 + nd;
        float a0 = 0.f, a1 = 0.f, s0 = 0.f, s1 = 0.f;
        if (node < Ntot) {
            int p0 = __shfl_sync(0xffffffffu, (lane == 0) ? g_ptr[node] : 0, 0);
            int p1 = __shfl_sync(0xffffffffu, (lane == 0) ? g_ptr[node + 1] : 0, 0);
            for (int e = p0; e < p1; e++) {
                size_t r = (size_t)g_adj[e] * 64;
                a0 += g_H1[r + lane];
                a1 += g_H1[r + 32 + lane];
            }
            size_t rn = (size_t)node * 64;
            s0 = g_H1[rn + lane];
            s1 = g_H1[rn + 32 + lane];
        }
        A1[lane * 68 + nd]        = a0;
        A1[(lane + 32) * 68 + nd] = a1;
        A2[lane * 68 + nd]        = s0;
        A2[(lane + 32) * 68 + nd] = s1;
    }
    for (int idx = tid; idx < 4096; idx += 256) Ws[idx] = Wr1[idx];
    __syncthreads();

    // phase A: H2 = relu(agg@Wr1 + self@Wo1 + b1)
    unsigned long long acc[4][2] = {{0,0},{0,0},{0,0},{0,0}};
    gemm_acc2<64>(A1, Ws, acc, tid);
    __syncthreads();
    for (int idx = tid; idx < 4096; idx += 256) Ws[idx] = Wo1[idx];
    __syncthreads();
    gemm_acc2<64>(A2, Ws, acc, tid);
    // write H2 directly TRANSPOSED into A1 (k-major): A1[k*68 + nd], k=4*tj+c, nd=4*ti+r
    {
        float4 bb = *(const float4*)&b1[4 * tj];
        #pragma unroll
        for (int r = 0; r < 4; r++) {
            float2 lo = unpack2(acc[r][0]), hi = unpack2(acc[r][1]);
            float hv[4];
            hv[0] = fmaxf(lo.x + bb.x, 0.f); hv[1] = fmaxf(lo.y + bb.y, 0.f);
            hv[2] = fmaxf(hi.x + bb.z, 0.f); hv[3] = fmaxf(hi.y + bb.w, 0.f);
            int nd = 4 * ti + r;
            #pragma unroll
            for (int c = 0; c < 4; c++) A1[(4 * tj + c) * 68 + nd] = hv[c];
        }
    }
    __syncthreads();

    // phase B: EMB = normalize(X@We[0:32] + H1@We[32:96] + H2@We[96:160] + be)
    unsigned long long acc2[4][2] = {{0,0},{0,0},{0,0},{0,0}};
    // chunk H2 (A1) x We[96:160]
    for (int idx = tid; idx < 4096; idx += 256) Ws[idx] = We[96 * 64 + idx];
    __syncthreads();
    gemm_acc2<64>(A1, Ws, acc2, tid);
    __syncthreads();
    // chunk H1 self (A2) x We[32:96]
    for (int idx = tid; idx < 4096; idx += 256) Ws[idx] = We[32 * 64 + idx];
    __syncthreads();
    gemm_acc2<64>(A2, Ws, acc2, tid);
    __syncthreads();
    // chunk X -> A2 (k-major 32 rows) x We[0:32]
    for (int idx = tid; idx < 2048; idx += 256) Ws[idx] = We[idx];
    for (int idx = tid; idx < 2048; idx += 256) {
        int nd = idx >> 5, k = idx & 31;
        int node = node0 + nd;
        A2[k * 68 + nd] = (node < Ntot) ? xrow(node, xs, xt, Ns)[k] : 0.f;
    }
    __syncthreads();
    gemm_acc2<32>(A2, Ws, acc2, tid);
    {
        float4 bb = *(const float4*)&be[4 * tj];
        #pragma unroll
        for (int r = 0; r < 4; r++) {
            int node = node0 + 4 * ti + r;
            float2 lo = unpack2(acc2[r][0]), hi = unpack2(acc2[r][1]);
            float4 o;
            o.x = lo.x + bb.x; o.y = lo.y + bb.y;
            o.z = hi.x + bb.z; o.w = hi.y + bb.w;
            float ss = o.x*o.x + o.y*o.y + o.z*o.z + o.w*o.w;
            #pragma unroll
            for (int d = 1; d < 16; d <<= 1) ss += __shfl_xor_sync(0xffffffffu, ss, d);
            float inv = rsqrtf(fmaxf(ss, 1e-24f));
            o.x *= inv; o.y *= inv; o.z *= inv; o.w *= inv;
            if (node < Ntot) *(float4*)&g_EMB[(size_t)node * 64 + 4 * tj] = o;
        }
    }
}

// ---------------- per-pair: cost/K + Sinkhorn + gamma/cost/geds (512 threads) ----------------
// rows of g_EMB and g_virt are unit-norm -> d = 2 - 2*dot
__global__ __launch_bounds__(512) void k_pair(const int* __restrict__ ls, const int* __restrict__ lt,
        int Ns, float* __restrict__ gamma, float* __restrict__ cost, float* __restrict__ geds2) {
    extern __shared__ float sm[];
    float* Km   = sm;               // [192][192]
    float* Ssub = sm + 36864;       // [64][68]
    float* Tsub = Ssub + 4352;      // 2 x [64][68]
    float* uu   = Tsub + 8704;      // [192]
    float* vv   = uu + 192;         // [192]
    float* vp   = vv + 192;         // [192]
    float* red  = vp + 192;         // [512]

    int p = g_order[blockIdx.x];
    int tid = threadIdx.x;
    int n = ls[p], m = lt[p], q = 192 - n;
    int offs = g_offs[p], offt = g_offt[p];
    const float* EB = g_EMB;

    for (int i = tid; i < 192; i += 512) {
        uu[i] = 1.0f / 192.0f;
        vv[i] = (i >= n && q > 0) ? (192.0f / (float)q) : 0.f;
    }

    // cost/K for real tiles (two 64x64 tiles concurrently, one per 256-thread group)
    int g = tid >> 8, lt5 = tid & 255;
    int ti = lt5 >> 4, tj = lt5 & 15;
    float* Tg = Tsub + g * 4352;
    int ntile = (n + 63) >> 6;

    for (int it_i = 0; it_i < ntile; it_i++) {
        int i0 = it_i << 6;
        __syncthreads();
        for (int idx = tid; idx < 4096; idx += 512) {
            int nd = idx >> 6, k = idx & 63;
            int i = i0 + nd; if (i >= n) i = n - 1;
            Ssub[k * 68 + nd] = EB[(size_t)(offs + i) * 64 + k];
        }
        for (int jj = 0; jj < ntile; jj += 2) {
            int jt = jj + g;
            bool mine = (jt < ntile);
            int j0 = jt << 6;
            __syncthreads();
            if (mine) {
                for (int idx = lt5; idx < 4096; idx += 256) {
                    int nd = idx >> 6, k = idx & 63;
                    int j = j0 + nd;
                    const float* r = (j < m) ? (EB + (size_t)(Ns + offt + j) * 64) : g_virt;
                    Tg[k * 68 + nd] = r[k];
                }
            }
            __syncthreads();
            if (mine) {
                unsigned long long acc[4][2] = {{0,0},{0,0},{0,0},{0,0}};
                unsigned bbase = (unsigned)__cvta_generic_to_shared(Tg + 4 * tj);
                const float* ap = Ssub + 4 * ti;
                #pragma unroll 4
                for (int k = 0; k < 64; k++) {
                    float4 a = *(const float4*)(ap + k * 68);
                    unsigned long long b01, b23;
                    asm("ld.shared.v2.u64 {%0, %1}, [%2];" : "=l"(b01), "=l"(b23)
                        : "r"(bbase + (unsigned)(k * 272)));
                    unsigned long long a0 = splat2(a.x), a1 = splat2(a.y),
                                       a2 = splat2(a.z), a3 = splat2(a.w);
                    fma2(acc[0][0], a0, b01); fma2(acc[0][1], a0, b23);
                    fma2(acc[1][0], a1, b01); fma2(acc[1][1], a1, b23);
                    fma2(acc[2][0], a2, b01); fma2(acc[2][1], a2, b23);
                    fma2(acc[3][0], a3, b01); fma2(acc[3][1], a3, b23);
                }
                #pragma unroll
                for (int r = 0; r < 4; r++) {
                    int i = i0 + 4 * ti + r;
                    float2 lo = unpack2(acc[r][0]), hi = unpack2(acc[r][1]);
                    float af[4] = {lo.x, lo.y, hi.x, hi.y};
                    float kv[4];
                    #pragma unroll
                    for (int c = 0; c < 4; c++) {
                        int j = j0 + 4 * tj + c;
                        if (i < n && j < n) {
                            float d = fmaxf(2.0f - 2.0f * af[c], 1e-12f);
                            float cd = d * rsqrtf(d);
                            kv[c] = __expf(-10.0f * cd);
                        } else {
                            kv[c] = ((i >= n) && (j >= n)) ? 1.f : 0.f;
                        }
                    }
                    *(float4*)&Km[i * 192 + j0 + 4 * tj] = make_float4(kv[0], kv[1], kv[2], kv[3]);
                }
            }
        }
    }
    __syncthreads();

    // Sinkhorn on the n x n real block; pad u,v stationary; cross K = 0 exactly.
    int nh = (n >> 1) & ~1;   // even split point
    for (int it = 0; it < 8; it++) {
        // v-pass: columns, two row-halves in parallel
        float slo = 0.f;
        if (tid < 192) {
            int j = tid;
            if (j < n) {
                unsigned long long s2 = 0;
                for (int i = 0; i < nh; i += 2) {
                    unsigned long long kk = pack2(Km[i * 192 + j], Km[(i + 1) * 192 + j]);
                    unsigned long long u2 = *(const unsigned long long*)(uu + i);
                    fma2(s2, kk, u2);
                }
                float2 f = unpack2(s2);
                slo = f.x + f.y;
            }
        } else if (tid < 384) {
            int j = tid - 192;
            if (j < n) {
                unsigned long long s2 = 0;
                float st = 0.f;
                int i = nh;
                for (; i + 2 <= n; i += 2) {
                    unsigned long long kk = pack2(Km[i * 192 + j], Km[(i + 1) * 192 + j]);
                    unsigned long long u2 = *(const unsigned long long*)(uu + i);
                    fma2(s2, kk, u2);
                }
                if (i < n) st = Km[i * 192 + j] * uu[i];
                float2 f = unpack2(s2);
                vp[j] = f.x + f.y + st;
            }
        }
        __syncthreads();
        if (tid < 192 && tid < n) vv[tid] = 1.0f / (slo + vp[tid]);
        __syncthreads();
        // u-pass: diagonal-staggered thread-per-row, two column-halves in parallel
        float sA = 0.f;
        if (tid < 192) {
            int r = tid;
            if (r < n) {
                const float* row = Km + r * 192;
                int st = r & 31; if (st >= nh) st = 0;
                for (int k = st; k < nh; k++) sA = fmaf(row[k], vv[k], sA);
                for (int k = 0; k < st; k++) sA = fmaf(row[k], vv[k], sA);
            }
        } else if (tid < 384) {
            int r = tid - 192;
            if (r < n) {
                const float* row = Km + r * 192;
                int wd = n - nh;
                int so = r & 31; if (so >= wd) so = 0;
                int st = nh + so;
                float s = 0.f;
                for (int k = st; k < n; k++) s = fmaf(row[k], vv[k], s);
                for (int k = nh; k < st; k++) s = fmaf(row[k], vv[k], s);
                vp[r] = s;
            }
        }
        __syncthreads();
        if (tid < 192 && tid < n) uu[tid] = 1.0f / (sA + vp[tid]);
        __syncthreads();
    }

    // epilogue: gamma = u K v; cost = -0.1 ln K in-block, pattern elsewhere; geds
    float* costp = cost + (size_t)p * 36864;
    float* gamp  = gamma + (size_t)p * 36864;
    float loc = 0.f;
    for (int idx = tid; idx < 9216; idx += 512) {
        int i = idx / 48, jb = (idx - i * 48) * 4;
        float4 k4 = *(const float4*)&Km[i * 192 + jb];   // garbage outside real tiles: discarded
        float ui = uu[i];
        float kk[4] = {k4.x, k4.y, k4.z, k4.w};
        float gg[4], cc[4];
        #pragma unroll
        for (int c = 0; c < 4; c++) {
            int j = jb + c;
            bool inb = (i < n) && (j < n);
            bool pad = (i >= n) && (j >= n);
            float kv = inb ? kk[c] : (pad ? 1.f : 0.f);
            cc[c] = inb ? (-0.1f * __logf(kk[c])) : (pad ? 0.f : 1000.f);
            gg[c] = ui * kv * vv[j];
            loc += gg[c] * cc[c];
        }
        *(float4*)&gamp[i * 192 + jb]  = make_float4(gg[0], gg[1], gg[2], gg[3]);
        *(float4*)&costp[i * 192 + jb] = make_float4(cc[0], cc[1], cc[2], cc[3]);
    }
    red[tid] = loc;
    __syncthreads();
    #pragma unroll
    for (int s = 256; s; s >>= 1) { if (tid < s) red[tid] += red[tid + s]; __syncthreads(); }
    if (tid == 0) geds2[p] = red[0] / (float)(n + m);
}

extern "C" void kernel_launch(void* const* d_in, const int* in_sizes, int n_in,
                              void* d_out, int out_size) {
    const float* x_s     = (const float*)d_in[0];
    const float* x_t     = (const float*)d_in[1];
    const float* W_rel0  = (const float*)d_in[2];
    const float* b_rel0  = (const float*)d_in[3];
    const float* W_root0 = (const float*)d_in[4];
    const float* W_rel1  = (const float*)d_in[5];
    const float* b_rel1  = (const float*)d_in[6];
    const float* W_root1 = (const float*)d_in[7];
    const float* W_e     = (const float*)d_in[8];
    const float* b_e     = (const float*)d_in[9];
    const float* virt    = (const float*)d_in[10];
    const int* ei_s      = (const int*)d_in[11];
    const int* ei_t      = (const int*)d_in[12];
    const int* len_s     = (const int*)d_in[13];
    const int* len_t     = (const int*)d_in[14];

    int Ns = in_sizes[0] / 32, Nt = in_sizes[1] / 32;
    int Es = in_sizes[11] / 2, Et = in_sizes[12] / 2;
    int Ntot = Ns + Nt;
    int Etot = Es + Et;

    float* out   = (float*)d_out;
    float* gamma = out;
    float* cost  = out + (size_t)PTOT * 36864;
    float* geds2 = cost + (size_t)PTOT * 36864;

    cudaFuncSetAttribute(k_gnn12, cudaFuncAttributeMaxDynamicSharedMemorySize, 12800 * 4);
    cudaFuncSetAttribute(k_pair,  cudaFuncAttributeMaxDynamicSharedMemorySize, 51008 * 4);

    int NB = (Ntot + 1023) / 1024;
    k_all<<<NB, 1024>>>(len_s, len_t, virt, ei_s, Es, ei_t, Et, Ns, Ntot, NB, Etot);

    int gb = (Ntot + 63) / 64;
    k_gnn0<<<gb, 256>>>(W_rel0, W_root0, b_rel0, Ntot, x_s, x_t, Ns);
    k_gnn12<<<gb, 256, 12800 * 4>>>(W_rel1, W_root1, b_rel1, W_e, b_e, Ntot, x_s, x_t, Ns);

    k_pair<<<PTOT, 512, 51008 * 4>>>(len_s, len_t, Ns, gamma, cost, geds2);
}